// round 12
// baseline (speedup 1.0000x reference)
#include <cuda_runtime.h>
#include <cuda_bf16.h>

// BERTLatticeEmbedding: ragged segment mean-pool.
// hidden [B,S,H] f32, word_ids [B,S] int32 (sorted per row),
// out [B,T,H] f32. B=64, S=512, H=768, T=400.
//
// R8: R6 task shape (word-pair x half-row) + software pipelining: each warp
//     owns NT=4 grid-strided tasks and prefetches the next task's segment
//     boundaries while accumulating the current task's payload, hiding the
//     bounds-load latency behind payload loads.

#define B_DIM 64
#define S_DIM 512
#define H_DIM 768
#define T_DIM 400
#define H4    (H_DIM / 4)       // 192 float4 per row
#define HALF4 (H4 / 2)          // 96 float4 per half-row
#define TPB   256
#define NT    4                 // tasks per warp
#define TASKS_PER_B 400         // 200 word pairs * 2 halves
#define TOTAL_TASKS (B_DIM * TASKS_PER_B)   // 25600
#define NWARPS (TOTAL_TASKS / NT)           // 6400

__device__ int g_start[B_DIM * (T_DIM + 1)];

__global__ __launch_bounds__(512) void bounds_kernel(
    const int* __restrict__ word_ids)
{
    __shared__ int s_row[S_DIM];
    const int b   = blockIdx.x;
    const int tid = threadIdx.x;

    s_row[tid] = word_ids[b * S_DIM + tid];
    __syncthreads();

    if (tid <= T_DIM) {
        int lo = 0, hi = S_DIM;
        while (lo < hi) {
            int mid = (lo + hi) >> 1;
            if (s_row[mid] < tid) lo = mid + 1; else hi = mid;
        }
        g_start[b * (T_DIM + 1) + tid] = lo;
    }
}

__device__ __forceinline__ void f4add(float4& a, const float4 v) {
    a.x += v.x; a.y += v.y; a.z += v.z; a.w += v.w;
}
__device__ __forceinline__ void f4scale(float4& a, const float s) {
    a.x *= s; a.y *= s; a.z *= s; a.w *= s;
}

// Per-lane bounds fetch for a task: lanes 0..2 read start[w0 + lane].
__device__ __forceinline__ int fetch_bounds(int task, int lane) {
    const int b   = task / TASKS_PER_B;
    const int rem = task - b * TASKS_PER_B;
    const int w0  = (rem >> 1) * 2;
    return __ldg(g_start + b * (T_DIM + 1) + w0 + (lane < 2 ? lane : 2));
}

__global__ __launch_bounds__(TPB) void pool_kernel(
    const float* __restrict__ hidden,
    float* __restrict__ out)
{
    const int warp = threadIdx.x >> 5;
    const int lane = threadIdx.x & 31;
    const int wg   = blockIdx.x * (TPB / 32) + warp;   // 0 .. NWARPS-1
    const unsigned FULL = 0xffffffffu;

    int task = wg;
    int myb  = fetch_bounds(task, lane);

    #pragma unroll
    for (int k = 0; k < NT; ++k) {
        const int ntask = task + NWARPS;
        int myb_next = 0;
        if (k + 1 < NT) myb_next = fetch_bounds(ntask, lane);   // prefetch

        // Decode current task.
        const int b    = task / TASKS_PER_B;
        const int rem  = task - b * TASKS_PER_B;
        const int wp   = rem >> 1;
        const int half = rem & 1;
        const int w0   = wp * 2;
        const int off  = half * HALF4 + lane;

        const int s0 = __shfl_sync(FULL, myb, 0);
        const int s1 = __shfl_sync(FULL, myb, 1);
        const int s2 = __shfl_sync(FULL, myb, 2);

        const float4* __restrict__ hin =
            reinterpret_cast<const float4*>(hidden + (size_t)b * S_DIM * H_DIM) + off;

        const float4 Z = make_float4(0.f, 0.f, 0.f, 0.f);
        float4 A0 = Z, A1 = Z, A2 = Z;   // word w0
        float4 B0 = Z, B1 = Z, B2 = Z;   // word w0+1

        for (int s = s0; s < s2; s += 2) {
            const float4* q = hin + (size_t)s * H4;
            const bool has1 = (s + 1 < s2);
            float4 v0 = __ldcs(q);
            float4 v1 = __ldcs(q + 32);
            float4 v2 = __ldcs(q + 64);
            float4 u0, u1, u2;
            if (has1) {
                u0 = __ldcs(q + H4);
                u1 = __ldcs(q + H4 + 32);
                u2 = __ldcs(q + H4 + 64);
            }
            if (s < s1) { f4add(A0, v0); f4add(A1, v1); f4add(A2, v2); }
            else        { f4add(B0, v0); f4add(B1, v1); f4add(B2, v2); }
            if (has1) {
                if (s + 1 < s1) { f4add(A0, u0); f4add(A1, u1); f4add(A2, u2); }
                else            { f4add(B0, u0); f4add(B1, u1); f4add(B2, u2); }
            }
        }

        const int c0 = s1 - s0;
        const int c1 = s2 - s1;
        const float invA = 1.0f / (float)(c0 > 0 ? c0 : 1);
        const float invB = 1.0f / (float)(c1 > 0 ? c1 : 1);
        f4scale(A0, invA); f4scale(A1, invA); f4scale(A2, invA);
        f4scale(B0, invB); f4scale(B1, invB); f4scale(B2, invB);

        float4* __restrict__ opA =
            reinterpret_cast<float4*>(out + ((size_t)b * T_DIM + w0) * H_DIM) + off;
        float4* __restrict__ opB = opA + H4;
        __stcs(opA,      A0);
        __stcs(opA + 32, A1);
        __stcs(opA + 64, A2);
        __stcs(opB,      B0);
        __stcs(opB + 32, B1);
        __stcs(opB + 64, B2);

        myb  = myb_next;
        task = ntask;
    }
}

extern "C" void kernel_launch(void* const* d_in, const int* in_sizes, int n_in,
                              void* d_out, int out_size)
{
    const float* hidden   = (const float*)d_in[0];
    const int*   word_ids = (const int*)d_in[1];
    float* out = (float*)d_out;

    bounds_kernel<<<B_DIM, 512>>>(word_ids);

    pool_kernel<<<NWARPS / (TPB / 32), TPB>>>(hidden, out);
}

// round 13
// speedup vs baseline: 1.1106x; 1.1106x over previous
#include <cuda_runtime.h>
#include <cuda_bf16.h>

// BERTLatticeEmbedding: ragged segment mean-pool.
// hidden [B,S,H] f32, word_ids [B,S] int32 (sorted per row),
// out [B,T,H] f32. B=64, S=512, H=768, T=400.
//
// R9: R6 task shape (word-pair x half-row, 6-load bursts) with:
//  - block-cooperative bounds: the 8 warps of a block cover 4 adjacent word
//    pairs -> 9 contiguous boundaries, fetched by one coalesced 9-thread load
//    into SMEM (kills the per-warp ~600-cycle dependent bounds chain).
//  - write-back stores (output fits in L2; defer evictions, free DRAM for reads).

#define B_DIM 64
#define S_DIM 512
#define H_DIM 768
#define T_DIM 400
#define H4    (H_DIM / 4)       // 192 float4 per row
#define HALF4 (H4 / 2)          // 96 float4 per half-row
#define TPB   256               // 8 warps
#define TASKS_PER_B 400         // 200 word pairs * 2 halves
#define BLOCKS_PER_B (TASKS_PER_B / (TPB / 32))   // 50

__device__ int g_start[B_DIM * (T_DIM + 1)];

__global__ __launch_bounds__(512) void bounds_kernel(
    const int* __restrict__ word_ids)
{
    __shared__ int s_row[S_DIM];
    const int b   = blockIdx.x;
    const int tid = threadIdx.x;

    s_row[tid] = word_ids[b * S_DIM + tid];
    __syncthreads();

    if (tid <= T_DIM) {
        int lo = 0, hi = S_DIM;
        while (lo < hi) {
            int mid = (lo + hi) >> 1;
            if (s_row[mid] < tid) lo = mid + 1; else hi = mid;
        }
        g_start[b * (T_DIM + 1) + tid] = lo;
    }
}

__device__ __forceinline__ void f4add(float4& a, const float4 v) {
    a.x += v.x; a.y += v.y; a.z += v.z; a.w += v.w;
}
__device__ __forceinline__ void f4scale(float4& a, const float s) {
    a.x *= s; a.y *= s; a.z *= s; a.w *= s;
}

__global__ __launch_bounds__(TPB) void pool_kernel(
    const float* __restrict__ hidden,
    float* __restrict__ out)
{
    __shared__ int s_b[9];   // start[wbase .. wbase+8]

    const int b       = blockIdx.x / BLOCKS_PER_B;
    const int blk_in  = blockIdx.x - b * BLOCKS_PER_B;
    const int wbase   = blk_in * 8;          // 8 words per block (4 pairs)
    const int tid     = threadIdx.x;
    const int warp    = tid >> 5;
    const int lane    = tid & 31;

    if (tid < 9)
        s_b[tid] = __ldg(g_start + b * (T_DIM + 1) + wbase + tid);
    __syncthreads();

    const int pair = warp >> 1;               // 0..3
    const int half = warp & 1;
    const int w0   = wbase + pair * 2;
    const int off  = half * HALF4 + lane;

    const int s0 = s_b[pair * 2];
    const int s1 = s_b[pair * 2 + 1];
    const int s2 = s_b[pair * 2 + 2];

    const float4* __restrict__ hin =
        reinterpret_cast<const float4*>(hidden + (size_t)b * S_DIM * H_DIM) + off;

    const float4 Z = make_float4(0.f, 0.f, 0.f, 0.f);
    float4 A0 = Z, A1 = Z, A2 = Z;   // word w0
    float4 B0 = Z, B1 = Z, B2 = Z;   // word w0+1

    // Combined contiguous piece range [s0, s2); warp-uniform predicates.
    for (int s = s0; s < s2; s += 2) {
        const float4* q = hin + (size_t)s * H4;
        const bool has1 = (s + 1 < s2);
        float4 v0 = __ldcs(q);
        float4 v1 = __ldcs(q + 32);
        float4 v2 = __ldcs(q + 64);
        float4 u0, u1, u2;
        if (has1) {
            u0 = __ldcs(q + H4);
            u1 = __ldcs(q + H4 + 32);
            u2 = __ldcs(q + H4 + 64);
        }
        if (s < s1) { f4add(A0, v0); f4add(A1, v1); f4add(A2, v2); }
        else        { f4add(B0, v0); f4add(B1, v1); f4add(B2, v2); }
        if (has1) {
            if (s + 1 < s1) { f4add(A0, u0); f4add(A1, u1); f4add(A2, u2); }
            else            { f4add(B0, u0); f4add(B1, u1); f4add(B2, u2); }
        }
    }

    const int c0 = s1 - s0;
    const int c1 = s2 - s1;
    const float invA = 1.0f / (float)(c0 > 0 ? c0 : 1);
    const float invB = 1.0f / (float)(c1 > 0 ? c1 : 1);
    f4scale(A0, invA); f4scale(A1, invA); f4scale(A2, invA);
    f4scale(B0, invB); f4scale(B1, invB); f4scale(B2, invB);

    // Write-back stores: output (78MB) fits in L2; defer DRAM eviction.
    float4* __restrict__ opA =
        reinterpret_cast<float4*>(out + ((size_t)b * T_DIM + w0) * H_DIM) + off;
    float4* __restrict__ opB = opA + H4;
    opA[0]  = A0;
    opA[32] = A1;
    opA[64] = A2;
    opB[0]  = B0;
    opB[32] = B1;
    opB[64] = B2;
}

extern "C" void kernel_launch(void* const* d_in, const int* in_sizes, int n_in,
                              void* d_out, int out_size)
{
    const float* hidden   = (const float*)d_in[0];
    const int*   word_ids = (const int*)d_in[1];
    float* out = (float*)d_out;

    bounds_kernel<<<B_DIM, 512>>>(word_ids);

    pool_kernel<<<B_DIM * BLOCKS_PER_B, TPB>>>(hidden, out);   // 3200 blocks
}